// round 5
// baseline (speedup 1.0000x reference)
#include <cuda_runtime.h>
#include <math.h>

#define NC 1000
#define NA 64

// Scratch for pp = rowsum(W * P). __device__ global (no allocation allowed).
__device__ float g_pp[1024];

// Kernel 1: pp[row] = sum_k W[row,k] * P[row,k].  One warp per row, float2 per
// lane, fixed-order shuffle tree => deterministic. 125 blocks -> full-chip BW.
__global__ void pp_kernel(const float* __restrict__ W, const float* __restrict__ P) {
    int warp = (blockIdx.x * blockDim.x + threadIdx.x) >> 5;
    int lane = threadIdx.x & 31;
    if (warp >= NC) return;
    const float2* w2 = reinterpret_cast<const float2*>(W + warp * NA);
    const float2* p2 = reinterpret_cast<const float2*>(P + warp * NA);
    float2 w = w2[lane];
    float2 p = p2[lane];
    float s = w.x * p.x + w.y * p.y;
    #pragma unroll
    for (int off = 16; off; off >>= 1)
        s += __shfl_down_sync(0xffffffffu, s, off);
    if (lane == 0) g_pp[warp] = s;
}

// Kernel 2: register-resident solver with a BRANCHLESS per-class scan.
//   q = softmax(pp); c = argmax(p0).
//   Per class j (one thread): walk the exact float omega recurrence; record
//   (predicated SELs, no divergent breaks) the first step where j no longer
//   beats c, or the forced underflow stop.  Warp-uniform early exit every 8
//   steps via __all_sync.  istar = max_j t_j carrying omega_star.
__global__ __launch_bounds__(1024) void solve_kernel(const float* __restrict__ p0,
                                                     const float* __restrict__ omega,
                                                     float* __restrict__ out) {
    __shared__ float red_a[32], red_b[32], red_c[32];
    __shared__ int   red_i[32];
    __shared__ float s_maxpp, s_sumexp, s_p0c, s_ppc, s_omstar;
    __shared__ int   s_c;

    const unsigned FULL = 0xffffffffu;
    int tid  = threadIdx.x;
    int lane = tid & 31;
    int wid  = tid >> 5;
    bool live = (tid < NC);

    float w0 = omega[0];
    w0 = fminf(fmaxf(w0, 0.0f), 1.0f);

    float p0v = live ? p0[tid]   : -INFINITY;
    float ppv = live ? g_pp[tid] : -INFINITY;

    // ---- Phase A: max(pp)  +  argmax(p0) carrying pp[c] (one sync pair) ----
    {
        float m  = ppv;
        float av = p0v;
        int   ai = tid;
        float aw = ppv;
        #pragma unroll
        for (int off = 16; off; off >>= 1) {
            m = fmaxf(m, __shfl_down_sync(FULL, m, off));
            float ov = __shfl_down_sync(FULL, av, off);
            int   oi = __shfl_down_sync(FULL, ai, off);
            float ow = __shfl_down_sync(FULL, aw, off);
            if (ov > av || (ov == av && oi < ai)) { av = ov; ai = oi; aw = ow; }
        }
        if (lane == 0) { red_a[wid] = m; red_b[wid] = av; red_i[wid] = ai; red_c[wid] = aw; }
        __syncthreads();
        if (wid == 0) {
            float x  = red_a[lane];
            float bv = red_b[lane];
            int   bi = red_i[lane];
            float bw = red_c[lane];
            #pragma unroll
            for (int off = 16; off; off >>= 1) {
                x = fmaxf(x, __shfl_down_sync(FULL, x, off));
                float ov = __shfl_down_sync(FULL, bv, off);
                int   oi = __shfl_down_sync(FULL, bi, off);
                float ow = __shfl_down_sync(FULL, bw, off);
                if (ov > bv || (ov == bv && oi < bi)) { bv = ov; bi = oi; bw = ow; }
            }
            if (lane == 0) { s_maxpp = x; s_c = bi; s_p0c = bv; s_ppc = bw; }
        }
        __syncthreads();
    }

    // ---- Phase B: sum(exp(pp - max)) ----
    float e = live ? expf(ppv - s_maxpp) : 0.0f;
    {
        float s = e;
        #pragma unroll
        for (int off = 16; off; off >>= 1)
            s += __shfl_down_sync(FULL, s, off);
        if (lane == 0) red_a[wid] = s;
        __syncthreads();
        if (wid == 0) {
            float x = red_a[lane];
            #pragma unroll
            for (int off = 16; off; off >>= 1)
                x += __shfl_down_sync(FULL, x, off);
            if (lane == 0) s_sumexp = x;
        }
        __syncthreads();
    }
    float qv  = e / s_sumexp;
    int   c   = s_c;
    float p0c = s_p0c;
    float qc  = expf(s_ppc - s_maxpp) / s_sumexp;

    // ---- Branchless scan over the exact float omega recurrence ----
    // t = first i where class j does NOT beat c in argmax order
    //     (j<c: beats means vj >= vc ; j>c: beats means vj > vc),
    //     capped by the forced underflow stop at the last valid i.
    // Sequence length n <= 101 (w0 <= 1.0, step 0.01) < 128 = loop cap.
    bool islt    = (tid < c);
    bool stopped = !live || (tid == c);  // c and dead lanes: dormant, t=0
    int   t   = 0;
    float tom = w0;
    float cur = w0;

    #pragma unroll
    for (int chunk = 0; chunk < 16; ++chunk) {
        if (__all_sync(FULL, stopped)) break;   // warp-uniform early exit
        #pragma unroll
        for (int u = 0; u < 8; ++u) {
            int i = chunk * 8 + u;
            float onem = 1.0f - cur;
            float vc = onem * p0c + cur * qc;
            float vj = onem * p0v + cur * qv;
            bool viol = islt ? (vj >= vc) : (vj > vc);
            bool hit  = !stopped && !viol;       // first non-violation
            if (hit) { t = i; tom = cur; }       // predicated SELs
            stopped = stopped || hit;
            float dec = cur - 0.01f;
            bool under  = (dec < 0.001f);
            bool forceh = !stopped && under;     // forced underflow stop
            if (forceh) { t = i; tom = cur; }
            stopped = stopped || under;          // sequence ended for everyone
            cur = dec;
        }
    }

    // ---- Phase C: istar = max(t), carrying omega_star ----
    {
        int   mt = t;
        float mo = tom;
        #pragma unroll
        for (int off = 16; off; off >>= 1) {
            int   ot = __shfl_down_sync(FULL, mt, off);
            float oo = __shfl_down_sync(FULL, mo, off);
            if (ot > mt) { mt = ot; mo = oo; }
        }
        if (lane == 0) { red_i[wid] = mt; red_a[wid] = mo; }
        __syncthreads();
        if (wid == 0) {
            int   xt = red_i[lane];
            float xo = red_a[lane];
            #pragma unroll
            for (int off = 16; off; off >>= 1) {
                int   ot = __shfl_down_sync(FULL, xt, off);
                float oo = __shfl_down_sync(FULL, xo, off);
                if (ot > xt) { xt = ot; xo = oo; }
            }
            if (lane == 0) s_omstar = xo;
        }
        __syncthreads();
    }

    // ---- Output: p = (1-omega*) * p0 + omega* * q, shape (1, NC) ----
    if (live) {
        float om = s_omstar;
        out[tid] = (1.0f - om) * p0v + om * qv;
    }
}

extern "C" void kernel_launch(void* const* d_in, const int* in_sizes, int n_in,
                              void* d_out, int out_size) {
    const float* p0 = (const float*)d_in[0];
    const float* P  = (const float*)d_in[1];
    const float* W  = (const float*)d_in[2];
    const float* om = (const float*)d_in[3];
    float* out = (float*)d_out;

    pp_kernel<<<125, 256>>>(W, P);
    solve_kernel<<<1, 1024>>>(p0, om, out);
}